// round 2
// baseline (speedup 1.0000x reference)
#include <cuda_runtime.h>
#include <cuda_bf16.h>
#include <math.h>

// Problem constants (fixed by setup_inputs)
#define BB   4
#define SS   8192
#define HH   16
#define DD   128
#define NB   64      // SS / 128
#define HID  32
#define HID2 16
#define KP   1024    // nb*nb*0.25
#define NGROUPS (BB*HH)   // 64
#define GSIZE   (NB*NB)   // 4096

// ---- scratch (device globals; no allocation allowed) ----
__device__ float g_avg [2][BB*NB*HH*DD];   // pooled q / k  (2 x 2MB)
__device__ float g_imp [2][BB*NB*HH];      // importance scores
__device__ float g_part[2][BB*NB*HH*HID];  // q_part / k_part
__device__ float g_scores[BB*HH*GSIZE];    // combined, flat-linear order

// ============================================================
// K1: block-mean pooling.  One warp per (tensor,b,n,h) row.
// Each lane sums one float4 column over the 128 rows of the block.
// ============================================================
__global__ void pool_kernel(const float* __restrict__ q, const float* __restrict__ k) {
    int task = blockIdx.x * 4 + (threadIdx.x >> 5);   // 0..8191
    int lane = threadIdx.x & 31;
    int t    = task >> 12;                            // 0=q, 1=k
    int row  = task & 4095;                           // (b*NB+n)*HH + h
    int b  = row >> 10;
    int nh = row & 1023;
    int n  = nh >> 4;
    int h  = nh & 15;

    const float* base = (t ? k : q);
    size_t off = (((size_t)(b*SS + n*128))*HH + h) * DD;
    const float4* src = (const float4*)(base + off);

    float4 acc = make_float4(0.f, 0.f, 0.f, 0.f);
    #pragma unroll 8
    for (int s = 0; s < 128; s++) {
        float4 v = src[(size_t)s*512 + lane];   // stride H*D = 2048 floats = 512 float4
        acc.x += v.x; acc.y += v.y; acc.z += v.z; acc.w += v.w;
    }
    const float r = 1.0f / 128.0f;
    float4 o = make_float4(acc.x*r, acc.y*r, acc.z*r, acc.w*r);
    ((float4*)g_avg[t])[(size_t)row*32 + lane] = o;
}

// ============================================================
// K2: importance MLP + int1 half-matmul.  One warp per row.
// ============================================================
__global__ void mlp_kernel(const float* __restrict__ w1, const float* __restrict__ b1,
                           const float* __restrict__ w2, const float* __restrict__ b2,
                           const float* __restrict__ w3, const float* __restrict__ b3,
                           const float* __restrict__ wi1) {
    __shared__ float xs [4][DD];
    __shared__ float h1s[4][HID];
    __shared__ float h2s[4][HID2];

    int wi   = threadIdx.x >> 5;
    int lane = threadIdx.x & 31;
    int task = blockIdx.x * 4 + wi;       // 0..8191
    int t    = task >> 12;
    int row  = task & 4095;

    const float* x = g_avg[t] + (size_t)row * DD;
    ((float4*)xs[wi])[lane] = ((const float4*)x)[lane];
    __syncwarp();

    // h1 (imp layer 1) and interaction part, output channel = lane (32 channels)
    float a1 = b1[lane];
    float ap = 0.f;
    const float* wi1t = wi1 + (t ? DD*HID : 0);   // w_int1[:D] for q, [D:] for k
    #pragma unroll 8
    for (int d = 0; d < DD; d++) {
        float xd = xs[wi][d];
        a1 = fmaf(xd, w1  [d*HID + lane], a1);
        ap = fmaf(xd, wi1t[d*HID + lane], ap);
    }
    a1 = fmaxf(a1, 0.f);
    h1s[wi][lane] = a1;
    g_part[t][(size_t)row*HID + lane] = ap;
    __syncwarp();

    if (lane < HID2) {
        float a2 = b2[lane];
        #pragma unroll
        for (int c = 0; c < HID; c++) a2 = fmaf(h1s[wi][c], w2[c*HID2 + lane], a2);
        h2s[wi][lane] = fmaxf(a2, 0.f);
    }
    __syncwarp();

    if (lane == 0) {
        float a3 = b3[0];
        #pragma unroll
        for (int c = 0; c < HID2; c++) a3 = fmaf(h2s[wi][c], w3[c], a3);
        g_imp[t][row] = 1.0f / (1.0f + expf(-a3));
    }
}

// ============================================================
// K3: interaction + combined score.
// Block = (b, h, i_tile of 16).  kp for all 64 j in smem (padded rows),
// qp for 16 i's.  256 threads x 4 (i,j) pairs each.
// ============================================================
__global__ void inter_kernel(const float* __restrict__ bi1,
                             const float* __restrict__ wi2,
                             const float* __restrict__ bi2) {
    __shared__ float qp[16*HID];
    __shared__ float kp[64*33];         // padded to 33 to avoid bank conflicts
    __shared__ float qi[16], ki[64], bbf[HID], wwf[HID];

    int blk  = blockIdx.x;              // 0..255
    int b    = blk >> 6;
    int rest = blk & 63;
    int h    = rest >> 2;
    int it   = rest & 3;                // i tile (16 rows each)
    int tid  = threadIdx.x;

    for (int idx = tid; idx < 64*HID; idx += 256) {
        int j = idx >> 5, c = idx & 31;
        kp[j*33 + c] = g_part[1][(((size_t)b*NB + j)*HH + h)*HID + c];
    }
    for (int idx = tid; idx < 16*HID; idx += 256) {
        int il = idx >> 5, c = idx & 31;
        qp[idx] = g_part[0][(((size_t)b*NB + (it*16 + il))*HH + h)*HID + c];
    }
    if (tid < 64)        ki[tid]      = g_imp[1][(b*NB + tid)*HH + h];
    else if (tid < 80)   qi[tid-64]   = g_imp[0][(b*NB + it*16 + (tid-64))*HH + h];
    else if (tid < 112)  bbf[tid-80]  = bi1[tid-80];
    else if (tid < 144)  wwf[tid-112] = wi2[tid-112];
    __syncthreads();

    float bi2v = bi2[0];
    #pragma unroll
    for (int r = 0; r < 4; r++) {
        int p  = tid + 256*r;           // 0..1023 : (il, j)
        int il = p >> 6;
        int j  = p & 63;
        float acc = 0.f;
        #pragma unroll
        for (int c = 0; c < HID; c++)
            acc = fmaf(fmaxf(qp[il*HID + c] + kp[j*33 + c] + bbf[c], 0.f), wwf[c], acc);
        float inter = 1.0f / (1.0f + expf(-(acc + bi2v)));
        float score = (qi[il] * ki[j]) * inter;   // left-assoc like the reference broadcast
        int i = it*16 + il;
        g_scores[((size_t)b << 16) + (size_t)i*1024 + j*16 + h] = score;
    }
}

// ============================================================
// K4: per-group top-1024 mask via 4-pass MSB radix select.
// All scores > 0 so float order == uint-bit order.
// Ties broken by lowest index (matches jax.lax.top_k).
// Output: float32 0.0/1.0 (bool reference canonicalized to f32).
// ============================================================
__global__ void topk_kernel(float* __restrict__ out) {
    __shared__ unsigned int keys[GSIZE];
    __shared__ unsigned int hist[256];
    __shared__ unsigned int cum [256];
    __shared__ int          eqc [256];
    __shared__ unsigned int s_prefix;
    __shared__ int          s_kk;

    int g   = blockIdx.x;     // (b*16 + x)
    int tid = threadIdx.x;    // 256 threads

    const float* src = g_scores + (size_t)g * GSIZE;
    for (int m = tid; m < GSIZE; m += 256) keys[m] = __float_as_uint(src[m]);
    if (tid == 0) { s_prefix = 0u; s_kk = KP; }
    __syncthreads();

    #pragma unroll
    for (int pass = 0; pass < 4; pass++) {
        int shift = 24 - pass*8;
        hist[tid] = 0;
        __syncthreads();
        unsigned int pf = s_prefix;
        for (int m = tid; m < GSIZE; m += 256) {
            unsigned int key = keys[m];
            bool match = (pass == 0) || ((key >> (shift + 8)) == pf);
            if (match) atomicAdd(&hist[(key >> shift) & 255u], 1u);
        }
        __syncthreads();
        // suffix sums: cum[i] = count of candidates with byte >= i
        cum[tid] = hist[tid];
        __syncthreads();
        for (int off = 1; off < 256; off <<= 1) {
            unsigned int v = (tid + off < 256) ? cum[tid + off] : 0u;
            __syncthreads();
            cum[tid] += v;
            __syncthreads();
        }
        int kk = s_kk;
        // unique tid: largest bin with cum >= kk (cum is non-increasing)
        if ((int)cum[tid] >= kk && (tid == 255 || (int)cum[tid + 1] < kk)) {
            s_prefix = (pf << 8) | (unsigned int)tid;
            s_kk     = kk - (tid == 255 ? 0 : (int)cum[tid + 1]);
        }
        __syncthreads();
    }

    unsigned int T = s_prefix;   // exact key of k-th largest
    int need = s_kk;             // how many == T to take, lowest index first

    // exclusive prefix count of equals; thread owns contiguous chunk of 16
    int base = tid * 16;
    int cnt  = 0;
    #pragma unroll
    for (int m = 0; m < 16; m++) cnt += (keys[base + m] == T);
    eqc[tid] = cnt;
    __syncthreads();
    for (int off = 1; off < 256; off <<= 1) {
        int v = (tid >= off) ? eqc[tid - off] : 0;
        __syncthreads();
        eqc[tid] += v;
        __syncthreads();
    }
    int rank = eqc[tid] - cnt;   // equals before this chunk

    float4* o = (float4*)(out + (size_t)g * GSIZE + base);
    float sel[16];
    #pragma unroll
    for (int m = 0; m < 16; m++) {
        unsigned int key = keys[base + m];
        float s = 0.0f;
        if (key > T) s = 1.0f;
        else if (key == T) { if (rank < need) s = 1.0f; rank++; }
        sel[m] = s;
    }
    #pragma unroll
    for (int v = 0; v < 4; v++)
        o[v] = make_float4(sel[v*4], sel[v*4+1], sel[v*4+2], sel[v*4+3]);
}

// ============================================================
extern "C" void kernel_launch(void* const* d_in, const int* in_sizes, int n_in,
                              void* d_out, int out_size) {
    const float* q      = (const float*)d_in[0];
    const float* k      = (const float*)d_in[1];
    const float* w_imp1 = (const float*)d_in[2];
    const float* b_imp1 = (const float*)d_in[3];
    const float* w_imp2 = (const float*)d_in[4];
    const float* b_imp2 = (const float*)d_in[5];
    const float* w_imp3 = (const float*)d_in[6];
    const float* b_imp3 = (const float*)d_in[7];
    const float* w_int1 = (const float*)d_in[8];
    const float* b_int1 = (const float*)d_in[9];
    const float* w_int2 = (const float*)d_in[10];
    const float* b_int2 = (const float*)d_in[11];

    pool_kernel<<<2048, 128>>>(q, k);
    mlp_kernel<<<2048, 128>>>(w_imp1, b_imp1, w_imp2, b_imp2, w_imp3, b_imp3, w_int1);
    inter_kernel<<<256, 256>>>(b_int1, w_int2, b_int2);
    topk_kernel<<<NGROUPS, 256>>>((float*)d_out);
}

// round 3
// speedup vs baseline: 1.1053x; 1.1053x over previous
#include <cuda_runtime.h>
#include <cuda_bf16.h>
#include <math.h>

// Problem constants (fixed by setup_inputs)
#define BB   4
#define SS   8192
#define HH   16
#define DD   128
#define NB   64      // SS / 128
#define HID  32
#define HID2 16
#define KP   1024    // nb*nb*0.25
#define NGROUPS (BB*HH)   // 64
#define GSIZE   (NB*NB)   // 4096

// ---- scratch (device globals; no allocation allowed) ----
__device__ float g_avg [2][BB*NB*HH*DD];   // pooled q / k  (2 x 2MB)
__device__ float g_imp [2][BB*NB*HH];      // importance scores
__device__ float g_part[2][BB*NB*HH*HID];  // q_part / k_part
__device__ float g_scores[BB*HH*GSIZE];    // combined, flat-linear order

// ============================================================
// K1: block-mean pooling.  One 512-thread block per (tensor, b, n):
// reads a fully contiguous 1MB region, 8KB per s-iteration.
// thread tid = h*32 + lane owns one float4 column; streaming loads.
// ============================================================
__global__ void pool_kernel(const float* __restrict__ q, const float* __restrict__ k) {
    int blk = blockIdx.x;            // 0..511
    int t   = blk >> 8;              // 0=q, 1=k
    int bn  = blk & 255;             // b*64 + n
    int tid = threadIdx.x;           // 0..511

    const float* base = (t ? k : q) + (size_t)bn * (128 * 2048);
    const float4* src = (const float4*)base + tid;   // one row = 512 float4 = 2048 floats

    float4 a0 = make_float4(0.f,0.f,0.f,0.f);
    float4 a1 = make_float4(0.f,0.f,0.f,0.f);
    #pragma unroll 16
    for (int s = 0; s < 128; s += 2) {
        float4 v0 = __ldcs(src + (size_t)s * 512);
        float4 v1 = __ldcs(src + (size_t)(s + 1) * 512);
        a0.x += v0.x; a0.y += v0.y; a0.z += v0.z; a0.w += v0.w;
        a1.x += v1.x; a1.y += v1.y; a1.z += v1.z; a1.w += v1.w;
    }
    const float r = 1.0f / 128.0f;
    float4 o = make_float4((a0.x+a1.x)*r, (a0.y+a1.y)*r, (a0.z+a1.z)*r, (a0.w+a1.w)*r);

    int h    = tid >> 5;
    int lane = tid & 31;
    int row  = bn * 16 + h;                 // (b*NB+n)*HH + h
    ((float4*)g_avg[t])[(size_t)row * 32 + lane] = o;
}

// ============================================================
// K2: importance MLP + int1 half-matmul.  One warp per row.
// ============================================================
__global__ void mlp_kernel(const float* __restrict__ w1, const float* __restrict__ b1,
                           const float* __restrict__ w2, const float* __restrict__ b2,
                           const float* __restrict__ w3, const float* __restrict__ b3,
                           const float* __restrict__ wi1) {
    __shared__ float xs [4][DD];
    __shared__ float h1s[4][HID];
    __shared__ float h2s[4][HID2];

    int wi   = threadIdx.x >> 5;
    int lane = threadIdx.x & 31;
    int task = blockIdx.x * 4 + wi;       // 0..8191
    int t    = task >> 12;
    int row  = task & 4095;

    const float* x = g_avg[t] + (size_t)row * DD;
    ((float4*)xs[wi])[lane] = ((const float4*)x)[lane];
    __syncwarp();

    float a1 = b1[lane];
    float ap = 0.f;
    const float* wi1t = wi1 + (t ? DD*HID : 0);   // w_int1[:D] for q, [D:] for k
    #pragma unroll 8
    for (int d = 0; d < DD; d++) {
        float xd = xs[wi][d];
        a1 = fmaf(xd, w1  [d*HID + lane], a1);
        ap = fmaf(xd, wi1t[d*HID + lane], ap);
    }
    a1 = fmaxf(a1, 0.f);
    h1s[wi][lane] = a1;
    g_part[t][(size_t)row*HID + lane] = ap;
    __syncwarp();

    if (lane < HID2) {
        float a2 = b2[lane];
        #pragma unroll
        for (int c = 0; c < HID; c++) a2 = fmaf(h1s[wi][c], w2[c*HID2 + lane], a2);
        h2s[wi][lane] = fmaxf(a2, 0.f);
    }
    __syncwarp();

    if (lane == 0) {
        float a3 = b3[0];
        #pragma unroll
        for (int c = 0; c < HID2; c++) a3 = fmaf(h2s[wi][c], w3[c], a3);
        g_imp[t][row] = 1.0f / (1.0f + expf(-a3));
    }
}

// ============================================================
// K3: interaction + combined score.
// ============================================================
__global__ void inter_kernel(const float* __restrict__ bi1,
                             const float* __restrict__ wi2,
                             const float* __restrict__ bi2) {
    __shared__ float qp[16*HID];
    __shared__ float kp[64*33];         // padded to 33 to avoid bank conflicts
    __shared__ float qi[16], ki[64], bbf[HID], wwf[HID];

    int blk  = blockIdx.x;              // 0..255
    int b    = blk >> 6;
    int rest = blk & 63;
    int h    = rest >> 2;
    int it   = rest & 3;                // i tile (16 rows each)
    int tid  = threadIdx.x;

    for (int idx = tid; idx < 64*HID; idx += 256) {
        int j = idx >> 5, c = idx & 31;
        kp[j*33 + c] = g_part[1][(((size_t)b*NB + j)*HH + h)*HID + c];
    }
    for (int idx = tid; idx < 16*HID; idx += 256) {
        int il = idx >> 5, c = idx & 31;
        qp[idx] = g_part[0][(((size_t)b*NB + (it*16 + il))*HH + h)*HID + c];
    }
    if (tid < 64)        ki[tid]      = g_imp[1][(b*NB + tid)*HH + h];
    else if (tid < 80)   qi[tid-64]   = g_imp[0][(b*NB + it*16 + (tid-64))*HH + h];
    else if (tid < 112)  bbf[tid-80]  = bi1[tid-80];
    else if (tid < 144)  wwf[tid-112] = wi2[tid-112];
    __syncthreads();

    float bi2v = bi2[0];
    #pragma unroll
    for (int r = 0; r < 4; r++) {
        int p  = tid + 256*r;           // 0..1023 : (il, j)
        int il = p >> 6;
        int j  = p & 63;
        float acc = 0.f;
        #pragma unroll
        for (int c = 0; c < HID; c++)
            acc = fmaf(fmaxf(qp[il*HID + c] + kp[j*33 + c] + bbf[c], 0.f), wwf[c], acc);
        float inter = 1.0f / (1.0f + expf(-(acc + bi2v)));
        float score = (qi[il] * ki[j]) * inter;
        int i = it*16 + il;
        g_scores[((size_t)b << 16) + (size_t)i*1024 + j*16 + h] = score;
    }
}

// ============================================================
// K4: per-group top-1024 mask via 4-pass MSB radix select.
// 512 threads; 8 keys per thread kept in REGISTERS.
// One warp-shuffle suffix scan per pass (3 barriers/pass).
// All scores >= 0 so float order == uint-bit order.
// ============================================================
__global__ void __launch_bounds__(512) topk_kernel(float* __restrict__ out) {
    __shared__ unsigned int hist[256];
    __shared__ unsigned int s_prefix;
    __shared__ int s_kk;
    __shared__ int warp_tot[16];

    int g    = blockIdx.x;            // 0..63 : (b*16 + x)
    int tid  = threadIdx.x;           // 0..511
    int lane = tid & 31;
    int wid  = tid >> 5;

    // load 8 contiguous keys into registers
    const float4* src = (const float4*)(g_scores + (size_t)g * GSIZE) + tid * 2;
    float4 v0 = src[0], v1 = src[1];
    unsigned int key[8];
    key[0]=__float_as_uint(v0.x); key[1]=__float_as_uint(v0.y);
    key[2]=__float_as_uint(v0.z); key[3]=__float_as_uint(v0.w);
    key[4]=__float_as_uint(v1.x); key[5]=__float_as_uint(v1.y);
    key[6]=__float_as_uint(v1.z); key[7]=__float_as_uint(v1.w);

    if (tid == 0) { s_prefix = 0u; s_kk = KP; }

    #pragma unroll
    for (int pass = 0; pass < 4; pass++) {
        int shift = 24 - pass * 8;
        if (tid < 256) hist[tid] = 0u;
        __syncthreads();
        unsigned int pf = s_prefix;
        #pragma unroll
        for (int m = 0; m < 8; m++) {
            unsigned int kk = key[m];
            bool match = (pass == 0) || ((kk >> (shift + 8)) == pf);
            if (match) atomicAdd(&hist[(kk >> shift) & 255u], 1u);
        }
        __syncthreads();
        if (wid == 0) {
            // lane owns bins [lane*8, lane*8+8)
            unsigned int v[8], tot = 0u;
            #pragma unroll
            for (int m = 0; m < 8; m++) { v[m] = hist[lane*8 + m]; tot += v[m]; }
            // inclusive suffix-scan of lane totals
            unsigned int suf = tot;
            #pragma unroll
            for (int off = 1; off < 32; off <<= 1) {
                unsigned int o = __shfl_down_sync(0xffffffffu, suf, off);
                if (lane + off < 32) suf += o;
            }
            unsigned int above = suf - tot;     // sum over lanes > lane
            int kcur = s_kk;
            unsigned int cum[8];
            unsigned int run = above;
            #pragma unroll
            for (int m = 7; m >= 0; m--) { run += v[m]; cum[m] = run; }
            #pragma unroll
            for (int m = 0; m < 8; m++) {
                unsigned int cnext = (m < 7) ? cum[m+1] : above;
                if ((int)cum[m] >= kcur && (int)cnext < kcur) {
                    s_prefix = (pf << 8) | (unsigned int)(lane*8 + m);
                    s_kk     = kcur - (int)cnext;
                }
            }
        }
        __syncthreads();
    }

    unsigned int T = s_prefix;    // exact key of the k-th largest
    int need = s_kk;              // number of ==T to keep, lowest index first

    // rank of my equals among all equals (thread chunks are contiguous/in order)
    int cnt = 0;
    #pragma unroll
    for (int m = 0; m < 8; m++) cnt += (key[m] == T);
    int x = cnt;
    #pragma unroll
    for (int off = 1; off < 32; off <<= 1) {
        int o = __shfl_up_sync(0xffffffffu, x, off);
        if (lane >= off) x += o;
    }
    if (lane == 31) warp_tot[wid] = x;
    __syncthreads();
    if (tid < 16) {
        int w = warp_tot[tid];
        #pragma unroll
        for (int off = 1; off < 16; off <<= 1) {
            int o = __shfl_up_sync(0x0000ffffu, w, off);
            if (tid >= off) w += o;
        }
        warp_tot[tid] = w;   // inclusive warp prefix
    }
    __syncthreads();
    int rank = (wid > 0 ? warp_tot[wid - 1] : 0) + (x - cnt);

    float sel[8];
    #pragma unroll
    for (int m = 0; m < 8; m++) {
        unsigned int kk = key[m];
        float s = 0.0f;
        if (kk > T) s = 1.0f;
        else if (kk == T) { if (rank < need) s = 1.0f; rank++; }
        sel[m] = s;
    }
    float4* o = (float4*)(out + (size_t)g * GSIZE) + tid * 2;
    o[0] = make_float4(sel[0], sel[1], sel[2], sel[3]);
    o[1] = make_float4(sel[4], sel[5], sel[6], sel[7]);
}

// ============================================================
extern "C" void kernel_launch(void* const* d_in, const int* in_sizes, int n_in,
                              void* d_out, int out_size) {
    const float* q      = (const float*)d_in[0];
    const float* k      = (const float*)d_in[1];
    const float* w_imp1 = (const float*)d_in[2];
    const float* b_imp1 = (const float*)d_in[3];
    const float* w_imp2 = (const float*)d_in[4];
    const float* b_imp2 = (const float*)d_in[5];
    const float* w_imp3 = (const float*)d_in[6];
    const float* b_imp3 = (const float*)d_in[7];
    const float* w_int1 = (const float*)d_in[8];
    const float* b_int1 = (const float*)d_in[9];
    const float* w_int2 = (const float*)d_in[10];
    const float* b_int2 = (const float*)d_in[11];

    pool_kernel<<<512, 512>>>(q, k);
    mlp_kernel<<<2048, 128>>>(w_imp1, b_imp1, w_imp2, b_imp2, w_imp3, b_imp3, w_int1);
    inter_kernel<<<256, 256>>>(b_int1, w_int2, b_int2);
    topk_kernel<<<NGROUPS, 512>>>((float*)d_out);
}

// round 4
// speedup vs baseline: 1.1263x; 1.0190x over previous
#include <cuda_runtime.h>
#include <cuda_bf16.h>
#include <math.h>

// Problem constants (fixed by setup_inputs)
#define BB   4
#define SS   8192
#define HH   16
#define DD   128
#define NB   64      // SS / 128
#define HID  32
#define HID2 16
#define KP   1024    // nb*nb*0.25
#define NGROUPS (BB*HH)   // 64
#define GSIZE   (NB*NB)   // 4096

// ---- scratch (device globals; no allocation allowed) ----
__device__ float g_imp [2][BB*NB*HH];      // importance scores
__device__ float g_part[2][BB*NB*HH*HID];  // q_part / k_part
__device__ float g_scores[BB*HH*GSIZE];    // combined, flat-linear order

// ============================================================
// K1: fused block-mean pooling + importance MLP + int1 half-matmul.
// One 512-thread block per (tensor, b, n): reads a contiguous 1MB
// region (streaming), pools 16 rows (one per head) into smem, then
// warps 0-3 run the MLP with 4-row register tiling (weights loaded
// once per 4 rows).
// ============================================================
__global__ void __launch_bounds__(512) pool_mlp_kernel(
    const float* __restrict__ q,  const float* __restrict__ k,
    const float* __restrict__ w1, const float* __restrict__ b1,
    const float* __restrict__ w2, const float* __restrict__ b2,
    const float* __restrict__ w3, const float* __restrict__ b3,
    const float* __restrict__ wi1)
{
    __shared__ float xs [16][DD];
    __shared__ float h1s[16][HID];
    __shared__ float h2s[16][HID2];

    int blk = blockIdx.x;            // 0..511
    int t   = blk >> 8;              // 0=q, 1=k
    int bn  = blk & 255;             // b*64 + n
    int tid = threadIdx.x;           // 0..511
    int h    = tid >> 5;
    int lane = tid & 31;

    const float* base = (t ? k : q) + (size_t)bn * (128 * 2048);
    const float4* src = (const float4*)base + tid;

    float4 a0 = make_float4(0.f,0.f,0.f,0.f);
    float4 a1 = make_float4(0.f,0.f,0.f,0.f);
    #pragma unroll 16
    for (int s = 0; s < 128; s += 2) {
        float4 v0 = __ldcs(src + (size_t)s * 512);
        float4 v1 = __ldcs(src + (size_t)(s + 1) * 512);
        a0.x += v0.x; a0.y += v0.y; a0.z += v0.z; a0.w += v0.w;
        a1.x += v1.x; a1.y += v1.y; a1.z += v1.z; a1.w += v1.w;
    }
    const float r = 1.0f / 128.0f;
    float4 o = make_float4((a0.x+a1.x)*r, (a0.y+a1.y)*r, (a0.z+a1.z)*r, (a0.w+a1.w)*r);
    ((float4*)xs[h])[lane] = o;
    __syncthreads();

    // ---- MLP: warps 0-3, each handles 4 rows with shared weight loads ----
    int w = tid >> 5;
    if (w < 4) {
        int r0 = w * 4;
        float a1v[4], apv[4];
        float b1l = b1[lane];
        #pragma unroll
        for (int i = 0; i < 4; i++) { a1v[i] = b1l; apv[i] = 0.f; }
        const float* wi1t = wi1 + (t ? DD*HID : 0);   // w_int1[:D] / [D:]
        #pragma unroll 4
        for (int d = 0; d < DD; d++) {
            float w1v = w1  [d*HID + lane];
            float wiv = wi1t[d*HID + lane];
            #pragma unroll
            for (int i = 0; i < 4; i++) {
                float xd = xs[r0 + i][d];
                a1v[i] = fmaf(xd, w1v, a1v[i]);
                apv[i] = fmaf(xd, wiv, apv[i]);
            }
        }
        #pragma unroll
        for (int i = 0; i < 4; i++) {
            int row = bn * 16 + r0 + i;
            g_part[t][(size_t)row * HID + lane] = apv[i];
            h1s[r0 + i][lane] = fmaxf(a1v[i], 0.f);
        }
        __syncwarp();
        if (lane < HID2) {
            #pragma unroll
            for (int i = 0; i < 4; i++) {
                float a2 = b2[lane];
                #pragma unroll
                for (int c = 0; c < HID; c++)
                    a2 = fmaf(h1s[r0 + i][c], w2[c*HID2 + lane], a2);
                h2s[r0 + i][lane] = fmaxf(a2, 0.f);
            }
        }
        __syncwarp();
        if (lane < 4) {
            float a3 = b3[0];
            #pragma unroll
            for (int c = 0; c < HID2; c++)
                a3 = fmaf(h2s[r0 + lane][c], w3[c], a3);
            g_imp[t][bn * 16 + r0 + lane] = 1.0f / (1.0f + expf(-a3));
        }
    }
}

// ============================================================
// K2: interaction + combined score.
// Block = (b, h, i_tile of 16).  kp in smem (padded rows), bb/ww in
// registers via full unroll, qp broadcast -> 2 LDS per c-step.
// ============================================================
__global__ void __launch_bounds__(256) inter_kernel(
    const float* __restrict__ bi1,
    const float* __restrict__ wi2,
    const float* __restrict__ bi2)
{
    __shared__ float qp[16*HID];
    __shared__ float kp[64*33];         // padded to 33: conflict-free
    __shared__ float qi[16], ki[64];

    int blk  = blockIdx.x;              // 0..255
    int b    = blk >> 6;
    int rest = blk & 63;
    int h    = rest >> 2;
    int it   = rest & 3;                // i tile (16 rows each)
    int tid  = threadIdx.x;

    for (int idx = tid; idx < 64*HID; idx += 256) {
        int j = idx >> 5, c = idx & 31;
        kp[j*33 + c] = g_part[1][(((size_t)b*NB + j)*HH + h)*HID + c];
    }
    for (int idx = tid; idx < 16*HID; idx += 256) {
        int il = idx >> 5, c = idx & 31;
        qp[idx] = g_part[0][(((size_t)b*NB + (it*16 + il))*HH + h)*HID + c];
    }
    if (tid < 64)       ki[tid]    = g_imp[1][(b*NB + tid)*HH + h];
    else if (tid < 80)  qi[tid-64] = g_imp[0][(b*NB + it*16 + (tid-64))*HH + h];

    float bbv[HID], wwv[HID];
    #pragma unroll
    for (int c = 0; c < HID; c++) { bbv[c] = bi1[c]; wwv[c] = wi2[c]; }
    float bi2v = bi2[0];
    __syncthreads();

    #pragma unroll
    for (int rr = 0; rr < 4; rr++) {
        int p  = tid + 256*rr;          // 0..1023 : (il, j)
        int il = p >> 6;
        int j  = p & 63;
        float acc = 0.f;
        #pragma unroll
        for (int c = 0; c < HID; c++)
            acc = fmaf(fmaxf((qp[il*HID + c] + kp[j*33 + c]) + bbv[c], 0.f), wwv[c], acc);
        float inter = 1.0f / (1.0f + expf(-(acc + bi2v)));
        float score = (qi[il] * ki[j]) * inter;
        int i = it*16 + il;
        g_scores[((size_t)b << 16) + (size_t)i*1024 + j*16 + h] = score;
    }
}

// ============================================================
// K3: per-group top-1024 mask via 4-pass MSB radix select.
// 512 threads; 8 keys/thread in registers.  Histogram uses
// warp-aggregated atomics (__match_any_sync) because score
// exponents cluster into few bins.
// ============================================================
__global__ void __launch_bounds__(512) topk_kernel(float* __restrict__ out) {
    __shared__ unsigned int hist[256];
    __shared__ unsigned int s_prefix;
    __shared__ int s_kk;
    __shared__ int warp_tot[16];

    int g    = blockIdx.x;            // 0..63
    int tid  = threadIdx.x;           // 0..511
    int lane = tid & 31;
    int wid  = tid >> 5;

    const float4* src = (const float4*)(g_scores + (size_t)g * GSIZE) + tid * 2;
    float4 v0 = src[0], v1 = src[1];
    unsigned int key[8];
    key[0]=__float_as_uint(v0.x); key[1]=__float_as_uint(v0.y);
    key[2]=__float_as_uint(v0.z); key[3]=__float_as_uint(v0.w);
    key[4]=__float_as_uint(v1.x); key[5]=__float_as_uint(v1.y);
    key[6]=__float_as_uint(v1.z); key[7]=__float_as_uint(v1.w);

    if (tid == 0) { s_prefix = 0u; s_kk = KP; }

    #pragma unroll
    for (int pass = 0; pass < 4; pass++) {
        int shift = 24 - pass * 8;
        if (tid < 256) hist[tid] = 0u;
        __syncthreads();
        unsigned int pf = s_prefix;
        #pragma unroll
        for (int m = 0; m < 8; m++) {
            unsigned int kk  = key[m];
            unsigned int bin = (kk >> shift) & 255u;
            bool match = (pass == 0) || ((kk >> (shift + 8)) == pf);
            unsigned int bal = __ballot_sync(0xffffffffu, match);
            if (match) {
                unsigned int same = __match_any_sync(bal, bin);
                if ((same & ((1u << lane) - 1u)) == 0u)   // leader = lowest lane
                    atomicAdd(&hist[bin], __popc(same));
            }
        }
        __syncthreads();
        if (wid == 0) {
            unsigned int v[8], tot = 0u;
            #pragma unroll
            for (int m = 0; m < 8; m++) { v[m] = hist[lane*8 + m]; tot += v[m]; }
            unsigned int suf = tot;
            #pragma unroll
            for (int off = 1; off < 32; off <<= 1) {
                unsigned int o = __shfl_down_sync(0xffffffffu, suf, off);
                if (lane + off < 32) suf += o;
            }
            unsigned int above = suf - tot;
            int kcur = s_kk;
            unsigned int cum[8];
            unsigned int run = above;
            #pragma unroll
            for (int m = 7; m >= 0; m--) { run += v[m]; cum[m] = run; }
            #pragma unroll
            for (int m = 0; m < 8; m++) {
                unsigned int cnext = (m < 7) ? cum[m+1] : above;
                if ((int)cum[m] >= kcur && (int)cnext < kcur) {
                    s_prefix = (pf << 8) | (unsigned int)(lane*8 + m);
                    s_kk     = kcur - (int)cnext;
                }
            }
        }
        __syncthreads();
    }

    unsigned int T = s_prefix;    // exact key of the k-th largest
    int need = s_kk;              // number of ==T to keep, lowest index first

    int cnt = 0;
    #pragma unroll
    for (int m = 0; m < 8; m++) cnt += (key[m] == T);
    int x = cnt;
    #pragma unroll
    for (int off = 1; off < 32; off <<= 1) {
        int o = __shfl_up_sync(0xffffffffu, x, off);
        if (lane >= off) x += o;
    }
    if (lane == 31) warp_tot[wid] = x;
    __syncthreads();
    if (tid < 16) {
        int wv = warp_tot[tid];
        #pragma unroll
        for (int off = 1; off < 16; off <<= 1) {
            int o = __shfl_up_sync(0x0000ffffu, wv, off);
            if (tid >= off) wv += o;
        }
        warp_tot[tid] = wv;
    }
    __syncthreads();
    int rank = (wid > 0 ? warp_tot[wid - 1] : 0) + (x - cnt);

    float sel[8];
    #pragma unroll
    for (int m = 0; m < 8; m++) {
        unsigned int kk = key[m];
        float s = 0.0f;
        if (kk > T) s = 1.0f;
        else if (kk == T) { if (rank < need) s = 1.0f; rank++; }
        sel[m] = s;
    }
    float4* o = (float4*)(out + (size_t)g * GSIZE) + tid * 2;
    o[0] = make_float4(sel[0], sel[1], sel[2], sel[3]);
    o[1] = make_float4(sel[4], sel[5], sel[6], sel[7]);
}

// ============================================================
extern "C" void kernel_launch(void* const* d_in, const int* in_sizes, int n_in,
                              void* d_out, int out_size) {
    const float* q      = (const float*)d_in[0];
    const float* k      = (const float*)d_in[1];
    const float* w_imp1 = (const float*)d_in[2];
    const float* b_imp1 = (const float*)d_in[3];
    const float* w_imp2 = (const float*)d_in[4];
    const float* b_imp2 = (const float*)d_in[5];
    const float* w_imp3 = (const float*)d_in[6];
    const float* b_imp3 = (const float*)d_in[7];
    const float* w_int1 = (const float*)d_in[8];
    const float* b_int1 = (const float*)d_in[9];
    const float* w_int2 = (const float*)d_in[10];
    const float* b_int2 = (const float*)d_in[11];

    pool_mlp_kernel<<<512, 512>>>(q, k, w_imp1, b_imp1, w_imp2, b_imp2,
                                  w_imp3, b_imp3, w_int1);
    inter_kernel<<<256, 256>>>(b_int1, w_int2, b_int2);
    topk_kernel<<<NGROUPS, 512>>>((float*)d_out);
}

// round 5
// speedup vs baseline: 1.2144x; 1.0783x over previous
#include <cuda_runtime.h>
#include <cuda_bf16.h>
#include <math.h>

// Problem constants (fixed by setup_inputs)
#define BB   4
#define SS   8192
#define HH   16
#define DD   128
#define NB   64      // SS / 128
#define HID  32
#define HID2 16
#define KP   1024    // nb*nb*0.25
#define NGROUPS (BB*HH)   // 64
#define GSIZE   (NB*NB)   // 4096

// ---- scratch (device globals; no allocation allowed) ----
__device__ float g_imp [2][BB*NB*HH];      // importance scores
__device__ float g_part[2][BB*NB*HH*HID];  // q_part / k_part
__device__ float g_scores[BB*HH*GSIZE];    // combined, flat-linear order

// ============================================================
// K1: fused block-mean pooling + importance MLP + int1 half-matmul.
// One 256-thread block per (tensor, b, n): 4 blocks/SM -> all 512
// blocks resident in ONE wave (fixes the 1.73-wave quantization that
// held DRAM at 65%).  Each thread streams 2 float4 columns of the
// contiguous 1MB region; warps 0-3 then run the MLP with 4-row
// register tiling.
// ============================================================
__global__ void __launch_bounds__(256, 4) pool_mlp_kernel(
    const float* __restrict__ q,  const float* __restrict__ k,
    const float* __restrict__ w1, const float* __restrict__ b1,
    const float* __restrict__ w2, const float* __restrict__ b2,
    const float* __restrict__ w3, const float* __restrict__ b3,
    const float* __restrict__ wi1)
{
    __shared__ float xs [16][DD];
    __shared__ float h1s[16][HID];
    __shared__ float h2s[16][HID2];

    int blk = blockIdx.x;            // 0..511
    int t   = blk >> 8;              // 0=q, 1=k
    int bn  = blk & 255;             // b*64 + n
    int tid = threadIdx.x;           // 0..255

    const float* base = (t ? k : q) + (size_t)bn * (128 * 2048);
    const float4* src = (const float4*)base + tid;   // row = 512 float4

    float4 aA = make_float4(0.f,0.f,0.f,0.f);   // column tid
    float4 aB = make_float4(0.f,0.f,0.f,0.f);   // column tid+256
    #pragma unroll 8
    for (int s = 0; s < 128; s++) {
        float4 v0 = __ldcs(src + (size_t)s * 512);
        float4 v1 = __ldcs(src + (size_t)s * 512 + 256);
        aA.x += v0.x; aA.y += v0.y; aA.z += v0.z; aA.w += v0.w;
        aB.x += v1.x; aB.y += v1.y; aB.z += v1.z; aB.w += v1.w;
    }
    const float r = 1.0f / 128.0f;
    // column c: h = c>>5, d4 = c&31
    {
        int c0 = tid, c1 = tid + 256;
        ((float4*)xs[c0 >> 5])[c0 & 31] = make_float4(aA.x*r, aA.y*r, aA.z*r, aA.w*r);
        ((float4*)xs[c1 >> 5])[c1 & 31] = make_float4(aB.x*r, aB.y*r, aB.z*r, aB.w*r);
    }
    __syncthreads();

    // ---- MLP: warps 0-3, each handles 4 rows with shared weight loads ----
    int w    = tid >> 5;
    int lane = tid & 31;
    if (w < 4) {
        int r0 = w * 4;
        float a1v[4], apv[4];
        float b1l = b1[lane];
        #pragma unroll
        for (int i = 0; i < 4; i++) { a1v[i] = b1l; apv[i] = 0.f; }
        const float* wi1t = wi1 + (t ? DD*HID : 0);   // w_int1[:D] / [D:]
        #pragma unroll 4
        for (int d = 0; d < DD; d++) {
            float w1v = w1  [d*HID + lane];
            float wiv = wi1t[d*HID + lane];
            #pragma unroll
            for (int i = 0; i < 4; i++) {
                float xd = xs[r0 + i][d];
                a1v[i] = fmaf(xd, w1v, a1v[i]);
                apv[i] = fmaf(xd, wiv, apv[i]);
            }
        }
        #pragma unroll
        for (int i = 0; i < 4; i++) {
            int row = bn * 16 + r0 + i;
            g_part[t][(size_t)row * HID + lane] = apv[i];
            h1s[r0 + i][lane] = fmaxf(a1v[i], 0.f);
        }
        __syncwarp();
        if (lane < HID2) {
            #pragma unroll
            for (int i = 0; i < 4; i++) {
                float a2 = b2[lane];
                #pragma unroll
                for (int c = 0; c < HID; c++)
                    a2 = fmaf(h1s[r0 + i][c], w2[c*HID2 + lane], a2);
                h2s[r0 + i][lane] = fmaxf(a2, 0.f);
            }
        }
        __syncwarp();
        if (lane < 4) {
            float a3 = b3[0];
            #pragma unroll
            for (int c = 0; c < HID2; c++)
                a3 = fmaf(h2s[r0 + lane][c], w3[c], a3);
            g_imp[t][bn * 16 + r0 + lane] = 1.0f / (1.0f + expf(-a3));
        }
    }
}

// ============================================================
// K2: interaction + combined score.
// ============================================================
__global__ void __launch_bounds__(256) inter_kernel(
    const float* __restrict__ bi1,
    const float* __restrict__ wi2,
    const float* __restrict__ bi2)
{
    __shared__ float qp[16*HID];
    __shared__ float kp[64*33];         // padded to 33: conflict-free
    __shared__ float qi[16], ki[64];

    int blk  = blockIdx.x;              // 0..255
    int b    = blk >> 6;
    int rest = blk & 63;
    int h    = rest >> 2;
    int it   = rest & 3;                // i tile (16 rows each)
    int tid  = threadIdx.x;

    for (int idx = tid; idx < 64*HID; idx += 256) {
        int j = idx >> 5, c = idx & 31;
        kp[j*33 + c] = g_part[1][(((size_t)b*NB + j)*HH + h)*HID + c];
    }
    for (int idx = tid; idx < 16*HID; idx += 256) {
        int il = idx >> 5, c = idx & 31;
        qp[idx] = g_part[0][(((size_t)b*NB + (it*16 + il))*HH + h)*HID + c];
    }
    if (tid < 64)       ki[tid]    = g_imp[1][(b*NB + tid)*HH + h];
    else if (tid < 80)  qi[tid-64] = g_imp[0][(b*NB + it*16 + (tid-64))*HH + h];

    float bbv[HID], wwv[HID];
    #pragma unroll
    for (int c = 0; c < HID; c++) { bbv[c] = bi1[c]; wwv[c] = wi2[c]; }
    float bi2v = bi2[0];
    __syncthreads();

    #pragma unroll
    for (int rr = 0; rr < 4; rr++) {
        int p  = tid + 256*rr;          // 0..1023 : (il, j)
        int il = p >> 6;
        int j  = p & 63;
        float acc = 0.f;
        #pragma unroll
        for (int c = 0; c < HID; c++)
            acc = fmaf(fmaxf((qp[il*HID + c] + kp[j*33 + c]) + bbv[c], 0.f), wwv[c], acc);
        float inter = 1.0f / (1.0f + expf(-(acc + bi2v)));
        float score = (qi[il] * ki[j]) * inter;
        int i = it*16 + il;
        g_scores[((size_t)b << 16) + (size_t)i*1024 + j*16 + h] = score;
    }
}

// ============================================================
// K3: per-group top-1024 mask via 4-pass MSB radix select.
// Warp-aggregated histogram atomics (clustered exponents).
// ============================================================
__global__ void __launch_bounds__(512) topk_kernel(float* __restrict__ out) {
    __shared__ unsigned int hist[256];
    __shared__ unsigned int s_prefix;
    __shared__ int s_kk;
    __shared__ int warp_tot[16];

    int g    = blockIdx.x;            // 0..63
    int tid  = threadIdx.x;           // 0..511
    int lane = tid & 31;
    int wid  = tid >> 5;

    const float4* src = (const float4*)(g_scores + (size_t)g * GSIZE) + tid * 2;
    float4 v0 = src[0], v1 = src[1];
    unsigned int key[8];
    key[0]=__float_as_uint(v0.x); key[1]=__float_as_uint(v0.y);
    key[2]=__float_as_uint(v0.z); key[3]=__float_as_uint(v0.w);
    key[4]=__float_as_uint(v1.x); key[5]=__float_as_uint(v1.y);
    key[6]=__float_as_uint(v1.z); key[7]=__float_as_uint(v1.w);

    if (tid == 0) { s_prefix = 0u; s_kk = KP; }

    #pragma unroll
    for (int pass = 0; pass < 4; pass++) {
        int shift = 24 - pass * 8;
        if (tid < 256) hist[tid] = 0u;
        __syncthreads();
        unsigned int pf = s_prefix;
        #pragma unroll
        for (int m = 0; m < 8; m++) {
            unsigned int kk  = key[m];
            unsigned int bin = (kk >> shift) & 255u;
            bool match = (pass == 0) || ((kk >> (shift + 8)) == pf);
            unsigned int bal = __ballot_sync(0xffffffffu, match);
            if (match) {
                unsigned int same = __match_any_sync(bal, bin);
                if ((same & ((1u << lane) - 1u)) == 0u)   // leader = lowest lane
                    atomicAdd(&hist[bin], __popc(same));
            }
        }
        __syncthreads();
        if (wid == 0) {
            unsigned int v[8], tot = 0u;
            #pragma unroll
            for (int m = 0; m < 8; m++) { v[m] = hist[lane*8 + m]; tot += v[m]; }
            unsigned int suf = tot;
            #pragma unroll
            for (int off = 1; off < 32; off <<= 1) {
                unsigned int o = __shfl_down_sync(0xffffffffu, suf, off);
                if (lane + off < 32) suf += o;
            }
            unsigned int above = suf - tot;
            int kcur = s_kk;
            unsigned int cum[8];
            unsigned int run = above;
            #pragma unroll
            for (int m = 7; m >= 0; m--) { run += v[m]; cum[m] = run; }
            #pragma unroll
            for (int m = 0; m < 8; m++) {
                unsigned int cnext = (m < 7) ? cum[m+1] : above;
                if ((int)cum[m] >= kcur && (int)cnext < kcur) {
                    s_prefix = (pf << 8) | (unsigned int)(lane*8 + m);
                    s_kk     = kcur - (int)cnext;
                }
            }
        }
        __syncthreads();
    }

    unsigned int T = s_prefix;    // exact key of the k-th largest
    int need = s_kk;              // number of ==T to keep, lowest index first

    int cnt = 0;
    #pragma unroll
    for (int m = 0; m < 8; m++) cnt += (key[m] == T);
    int x = cnt;
    #pragma unroll
    for (int off = 1; off < 32; off <<= 1) {
        int o = __shfl_up_sync(0xffffffffu, x, off);
        if (lane >= off) x += o;
    }
    if (lane == 31) warp_tot[wid] = x;
    __syncthreads();
    if (tid < 16) {
        int wv = warp_tot[tid];
        #pragma unroll
        for (int off = 1; off < 16; off <<= 1) {
            int o = __shfl_up_sync(0x0000ffffu, wv, off);
            if (tid >= off) wv += o;
        }
        warp_tot[tid] = wv;
    }
    __syncthreads();
    int rank = (wid > 0 ? warp_tot[wid - 1] : 0) + (x - cnt);

    float sel[8];
    #pragma unroll
    for (int m = 0; m < 8; m++) {
        unsigned int kk = key[m];
        float s = 0.0f;
        if (kk > T) s = 1.0f;
        else if (kk == T) { if (rank < need) s = 1.0f; rank++; }
        sel[m] = s;
    }
    float4* o = (float4*)(out + (size_t)g * GSIZE) + tid * 2;
    o[0] = make_float4(sel[0], sel[1], sel[2], sel[3]);
    o[1] = make_float4(sel[4], sel[5], sel[6], sel[7]);
}

// ============================================================
extern "C" void kernel_launch(void* const* d_in, const int* in_sizes, int n_in,
                              void* d_out, int out_size) {
    const float* q      = (const float*)d_in[0];
    const float* k      = (const float*)d_in[1];
    const float* w_imp1 = (const float*)d_in[2];
    const float* b_imp1 = (const float*)d_in[3];
    const float* w_imp2 = (const float*)d_in[4];
    const float* b_imp2 = (const float*)d_in[5];
    const float* w_imp3 = (const float*)d_in[6];
    const float* b_imp3 = (const float*)d_in[7];
    const float* w_int1 = (const float*)d_in[8];
    const float* b_int1 = (const float*)d_in[9];
    const float* w_int2 = (const float*)d_in[10];
    const float* b_int2 = (const float*)d_in[11];

    pool_mlp_kernel<<<512, 256>>>(q, k, w_imp1, b_imp1, w_imp2, b_imp2,
                                  w_imp3, b_imp3, w_int1);
    inter_kernel<<<256, 256>>>(b_int1, w_int2, b_int2);
    topk_kernel<<<NGROUPS, 512>>>((float*)d_out);
}